// round 9
// baseline (speedup 1.0000x reference)
#include <cuda_runtime.h>
#include <cuda_bf16.h>
#include <cstdint>

// ---------------------------------------------------------------------------
// Bidirectional Mamba (bimamba v2) forward.
//   B=2, L=1024, d_model=768, d_inner=1536, d_state=16, d_conv=4, dt_rank=48
// GEMMs (in_proj, out_proj) via portable mma.sync m16n8k16 bf16 split-2
// (plain sm_103 target: tcgen05 unavailable, HMMA fallback path is).
// Everything else fp32 SIMT (audited pipeline).
// ---------------------------------------------------------------------------

#define BB    2
#define LL    1024
#define DM    768
#define DI    1536
#define NS    16
#define RDT   48
#define MROWS (BB*LL)          // 2048

// fp32 scratch
__device__ float g_xz[MROWS * 2 * DI];              // (2048, 3072)
__device__ float g_xc[2 * BB * DI * LL];            // [dir][b][d][l]
__device__ float g_zs[BB * DI * LL];                // [b][d][l]
__device__ float g_dt[2 * MROWS * RDT];
__device__ float g_Bc[2 * MROWS * NS];
__device__ float g_Cc[2 * MROWS * NS];
__device__ float g_delta[2 * BB * DI * LL];
__device__ float g_y[2 * BB * DI * LL];
__device__ float g_xpart[8 * 2 * MROWS * 80];

// bf16 split-2 operands for HMMA GEMMs
__device__ __nv_bfloat16 g_hh[MROWS * DM],  g_hl[MROWS * DM];     // hidden [m][k]
__device__ __nv_bfloat16 g_wih[2*DI * DM],  g_wil[2*DI * DM];     // in_proj W [n][k]
__device__ __nv_bfloat16 g_woh[DM * DI],    g_wol[DM * DI];       // out_proj W [n][k]
__device__ __nv_bfloat16 g_ych[MROWS * DI], g_ycl[MROWS * DI];    // combined y [m][k]

// ---------------------------------------------------------------------------
// 0. split fp32 -> bf16 hi/lo
// ---------------------------------------------------------------------------
__device__ __forceinline__ void split_body(const float* __restrict__ s,
                                           __nv_bfloat16* __restrict__ hi,
                                           __nv_bfloat16* __restrict__ lo, int n)
{
    int i = (blockIdx.x * blockDim.x + threadIdx.x) * 4;
    if (i >= n) return;
    float4 v = *(const float4*)(s + i);
    ushort4 H, L;
    {
        __nv_bfloat16 h = __float2bfloat16(v.x);
        H.x = __bfloat16_as_ushort(h);
        L.x = __bfloat16_as_ushort(__float2bfloat16(v.x - __bfloat162float(h)));
    }
    {
        __nv_bfloat16 h = __float2bfloat16(v.y);
        H.y = __bfloat16_as_ushort(h);
        L.y = __bfloat16_as_ushort(__float2bfloat16(v.y - __bfloat162float(h)));
    }
    {
        __nv_bfloat16 h = __float2bfloat16(v.z);
        H.z = __bfloat16_as_ushort(h);
        L.z = __bfloat16_as_ushort(__float2bfloat16(v.z - __bfloat162float(h)));
    }
    {
        __nv_bfloat16 h = __float2bfloat16(v.w);
        H.w = __bfloat16_as_ushort(h);
        L.w = __bfloat16_as_ushort(__float2bfloat16(v.w - __bfloat162float(h)));
    }
    *(ushort4*)((unsigned short*)hi + i) = H;
    *(ushort4*)((unsigned short*)lo + i) = L;
}
__global__ void k_split_h(const float* __restrict__ s)  { split_body(s, g_hh,  g_hl,  MROWS * DM); }
__global__ void k_split_wi(const float* __restrict__ s) { split_body(s, g_wih, g_wil, 2 * DI * DM); }
__global__ void k_split_wo(const float* __restrict__ s) { split_body(s, g_woh, g_wol, DM * DI); }

// ---------------------------------------------------------------------------
// mma.sync m16n8k16 row.col f32.bf16.bf16.f32
// ---------------------------------------------------------------------------
__device__ __forceinline__ void mma16816(float* c, const uint32_t* a, const uint32_t* b)
{
    asm volatile(
        "mma.sync.aligned.m16n8k16.row.col.f32.bf16.bf16.f32 "
        "{%0,%1,%2,%3}, {%4,%5,%6,%7}, {%8,%9}, {%0,%1,%2,%3};"
        : "+f"(c[0]), "+f"(c[1]), "+f"(c[2]), "+f"(c[3])
        : "r"(a[0]), "r"(a[1]), "r"(a[2]), "r"(a[3]), "r"(b[0]), "r"(b[1]));
}

// ---------------------------------------------------------------------------
// HMMA split-2 GEMM:  C[m][n] = sum_k A[m][k] * W[n][k]
// CTA tile 128x64, 8 warps (4 m x 2 n) of 32x32. K-chunk 32.
// smem rows padded to 40 bf16 (80B = 5*16B): uint4-aligned, LDS conflict-free
// (frag-load word offsets 20g+{0..3}, g=0..7 -> all 32 banks distinct).
// Per k16 step & warp: 2 m-frag x 4 n-frag x {AhBh, AhBl, AlBh} = 24 mma.
// ---------------------------------------------------------------------------
#define ASTR 40   // smem row stride in bf16

__device__ __forceinline__ void gemm_mma_body(const __nv_bfloat16* __restrict__ Ah,
                                              const __nv_bfloat16* __restrict__ Al,
                                              const __nv_bfloat16* __restrict__ Wh,
                                              const __nv_bfloat16* __restrict__ Wl,
                                              float* __restrict__ C,
                                              const int K, const int N)
{
    __shared__ __align__(16) __nv_bfloat16 sAh[128 * ASTR];
    __shared__ __align__(16) __nv_bfloat16 sAl[128 * ASTR];
    __shared__ __align__(16) __nv_bfloat16 sWh[64 * ASTR];
    __shared__ __align__(16) __nv_bfloat16 sWl[64 * ASTR];

    const int t    = threadIdx.x;
    const int wid  = t >> 5;
    const int lane = t & 31;
    const int wm   = wid & 3;            // 0..3 -> m offset wm*32
    const int wn   = wid >> 2;           // 0..1 -> n offset wn*32
    const int g    = lane >> 2;          // group 0..7
    const int t2   = (lane & 3) * 2;     // 0,2,4,6
    const int bm   = blockIdx.y * 128;
    const int bn   = blockIdx.x * 64;

    float acc[2][4][4];
#pragma unroll
    for (int mt = 0; mt < 2; mt++)
#pragma unroll
        for (int nt = 0; nt < 4; nt++)
#pragma unroll
            for (int q = 0; q < 4; q++) acc[mt][nt][q] = 0.f;

    const int NC = K / 32;
    for (int c = 0; c < NC; c++) {
        const int k0g = c * 32;
        // fill A: 128 rows x 32 bf16 = 512 uint4 per split; W: 64 x 32 = 256
        __syncthreads();
#pragma unroll
        for (int i = 0; i < 2; i++) {
            const int idx = t + 256 * i;          // 0..511
            const int row = idx >> 2, seg = idx & 3;
            const size_t gofs = (size_t)(bm + row) * K + k0g + seg * 8;
            *(uint4*)(sAh + row * ASTR + seg * 8) = *(const uint4*)(Ah + gofs);
            *(uint4*)(sAl + row * ASTR + seg * 8) = *(const uint4*)(Al + gofs);
        }
        {
            const int idx = t;                    // 0..255
            const int row = idx >> 2, seg = idx & 3;
            const size_t gofs = (size_t)(bn + row) * K + k0g + seg * 8;
            *(uint4*)(sWh + row * ASTR + seg * 8) = *(const uint4*)(Wh + gofs);
            *(uint4*)(sWl + row * ASTR + seg * 8) = *(const uint4*)(Wl + gofs);
        }
        __syncthreads();

#pragma unroll
        for (int ks = 0; ks < 2; ks++) {
            const int k0 = ks * 16;
            uint32_t ah[2][4], al[2][4], bh[4][2], bl[4][2];
#pragma unroll
            for (int mt = 0; mt < 2; mt++) {
                const int r0 = wm * 32 + mt * 16 + g;
                ah[mt][0] = *(const uint32_t*)(sAh + r0 * ASTR + k0 + t2);
                ah[mt][1] = *(const uint32_t*)(sAh + (r0 + 8) * ASTR + k0 + t2);
                ah[mt][2] = *(const uint32_t*)(sAh + r0 * ASTR + k0 + t2 + 8);
                ah[mt][3] = *(const uint32_t*)(sAh + (r0 + 8) * ASTR + k0 + t2 + 8);
                al[mt][0] = *(const uint32_t*)(sAl + r0 * ASTR + k0 + t2);
                al[mt][1] = *(const uint32_t*)(sAl + (r0 + 8) * ASTR + k0 + t2);
                al[mt][2] = *(const uint32_t*)(sAl + r0 * ASTR + k0 + t2 + 8);
                al[mt][3] = *(const uint32_t*)(sAl + (r0 + 8) * ASTR + k0 + t2 + 8);
            }
#pragma unroll
            for (int nt = 0; nt < 4; nt++) {
                const int n0 = wn * 32 + nt * 8 + g;
                bh[nt][0] = *(const uint32_t*)(sWh + n0 * ASTR + k0 + t2);
                bh[nt][1] = *(const uint32_t*)(sWh + n0 * ASTR + k0 + t2 + 8);
                bl[nt][0] = *(const uint32_t*)(sWl + n0 * ASTR + k0 + t2);
                bl[nt][1] = *(const uint32_t*)(sWl + n0 * ASTR + k0 + t2 + 8);
            }
#pragma unroll
            for (int mt = 0; mt < 2; mt++)
#pragma unroll
                for (int nt = 0; nt < 4; nt++) {
                    mma16816(acc[mt][nt], ah[mt], bh[nt]);
                    mma16816(acc[mt][nt], ah[mt], bl[nt]);
                    mma16816(acc[mt][nt], al[mt], bh[nt]);
                }
        }
    }

#pragma unroll
    for (int mt = 0; mt < 2; mt++) {
        const int row = bm + wm * 32 + mt * 16 + g;
#pragma unroll
        for (int nt = 0; nt < 4; nt++) {
            const int col = bn + wn * 32 + nt * 8 + t2;
            *(float2*)(C + (size_t)row * N + col)       = make_float2(acc[mt][nt][0], acc[mt][nt][1]);
            *(float2*)(C + (size_t)(row + 8) * N + col) = make_float2(acc[mt][nt][2], acc[mt][nt][3]);
        }
    }
}

__global__ void __launch_bounds__(256) k_gemm_in()
{ gemm_mma_body(g_hh, g_hl, g_wih, g_wil, g_xz, DM, 2 * DI); }

__global__ void __launch_bounds__(256) k_gemm_out(float* __restrict__ C)
{ gemm_mma_body(g_ych, g_ycl, g_woh, g_wol, C, DI, DM); }

// ---------------------------------------------------------------------------
// 2. conv (both dirs) + silu(z), transpose to channel-major.
// ---------------------------------------------------------------------------
__device__ __forceinline__ float siluf(float v) { return v / (1.f + __expf(-v)); }

__global__ void __launch_bounds__(256) k_conv_zs(const float* __restrict__ cw0,
                                                 const float* __restrict__ cb0,
                                                 const float* __restrict__ cw1,
                                                 const float* __restrict__ cb1)
{
    const int task = blockIdx.z % 3;
    const int b    = blockIdx.z / 3;
    const int l0   = blockIdx.x * 64;
    const int d0   = blockIdx.y * 32;
    __shared__ float sx[68][33];
    const int t = threadIdx.x;

    if (task < 2) {
        const int dir = task;
        for (int idx = t; idx < 67 * 32; idx += 256) {
            int j  = idx >> 5;
            int dc = idx & 31;
            int ls = l0 + j - 3;
            float v = 0.f;
            if (ls >= 0 && ls < LL) {
                int src = dir ? (LL - 1 - ls) : ls;
                v = g_xz[(b * LL + src) * (2 * DI) + d0 + dc];
            }
            sx[j][dc] = v;
        }
        __syncthreads();
        const float* cw = dir ? cw1 : cw0;
        const float* cb = dir ? cb1 : cb0;
        const int ll = t & 63;
        const int dg = t >> 6;
#pragma unroll
        for (int i = 0; i < 8; i++) {
            int dc = dg * 8 + i;
            int d  = d0 + dc;
            float acc = cb[d];
            acc = fmaf(cw[d * 4 + 0], sx[ll + 0][dc], acc);
            acc = fmaf(cw[d * 4 + 1], sx[ll + 1][dc], acc);
            acc = fmaf(cw[d * 4 + 2], sx[ll + 2][dc], acc);
            acc = fmaf(cw[d * 4 + 3], sx[ll + 3][dc], acc);
            g_xc[((dir * BB + b) * DI + d) * LL + l0 + ll] = siluf(acc);
        }
    } else {
        for (int idx = t; idx < 64 * 32; idx += 256) {
            int j  = idx >> 5;
            int dc = idx & 31;
            sx[j][dc] = g_xz[(b * LL + l0 + j) * (2 * DI) + DI + d0 + dc];
        }
        __syncthreads();
        const int ll = t & 63;
        const int dg = t >> 6;
#pragma unroll
        for (int i = 0; i < 8; i++) {
            int dc = dg * 8 + i;
            int d  = d0 + dc;
            g_zs[(b * DI + d) * LL + l0 + ll] = siluf(sx[ll][dc]);
        }
    }
}

// ---------------------------------------------------------------------------
// 3/4. x_dbl GEMM with K-split + reduce
// ---------------------------------------------------------------------------
__global__ void __launch_bounds__(256) k_xdbl(const float* __restrict__ W0,
                                              const float* __restrict__ W1)
{
    const int dir = blockIdx.z;
    const int bm  = blockIdx.x * 128;
    const int b   = bm >> 10;
    const int lb  = bm & 1023;
    const int ks  = blockIdx.y;
    const float* W = dir ? W1 : W0;

    __shared__ __align__(16) float As[8][128];
    __shared__ float Ws[8][80];
    const int t  = threadIdx.x;
    const int kl = t >> 5;
    const int lq = (t & 31) * 4;
    const int ty = t >> 4, tx = t & 15;

    float acc[8][5];
#pragma unroll
    for (int i = 0; i < 8; i++)
#pragma unroll
        for (int j = 0; j < 5; j++) acc[i][j] = 0.f;

    const int kend = ks * 192 + 192;
    for (int k0 = ks * 192; k0 < kend; k0 += 8) {
        float4 a4 = *(const float4*)(g_xc + ((dir * BB + b) * DI + k0 + kl) * LL + lb + lq);
        *(float4*)&As[kl][lq] = a4;
        if (t < 160) {
            int n  = t >> 1;
            int kq = (t & 1) * 4;
            float4 w4 = *(const float4*)(W + n * DI + k0 + kq);
            Ws[kq + 0][n] = w4.x; Ws[kq + 1][n] = w4.y;
            Ws[kq + 2][n] = w4.z; Ws[kq + 3][n] = w4.w;
        }
        __syncthreads();
#pragma unroll
        for (int kk = 0; kk < 8; kk++) {
            float br[5];
#pragma unroll
            for (int j = 0; j < 5; j++) br[j] = Ws[kk][tx * 5 + j];
#pragma unroll
            for (int i = 0; i < 8; i++) {
                float a = As[kk][ty * 8 + i];
#pragma unroll
                for (int j = 0; j < 5; j++) acc[i][j] = fmaf(a, br[j], acc[i][j]);
            }
        }
        __syncthreads();
    }
    float* part = g_xpart + ks * (2 * MROWS * 80);
#pragma unroll
    for (int i = 0; i < 8; i++) {
        int row = dir * MROWS + bm + ty * 8 + i;
#pragma unroll
        for (int j = 0; j < 5; j++)
            part[row * 80 + tx * 5 + j] = acc[i][j];
    }
}

__global__ void k_xred()
{
    int o = blockIdx.x * blockDim.x + threadIdx.x;
    if (o >= 2 * MROWS * 80) return;
    float s = 0.f;
#pragma unroll
    for (int p = 0; p < 8; p++) s += g_xpart[p * (2 * MROWS * 80) + o];
    int row = o / 80;
    int n   = o - row * 80;
    if (n < 48)       g_dt[row * RDT + n] = s;
    else if (n < 64)  g_Bc[row * NS + n - 48] = s;
    else              g_Cc[row * NS + n - 64] = s;
}

// ---------------------------------------------------------------------------
// 5. delta GEMM (K=48) + softplus, transposed store
// ---------------------------------------------------------------------------
__global__ void __launch_bounds__(256) k_delta(const float* __restrict__ dtw0,
                                               const float* __restrict__ dtb0,
                                               const float* __restrict__ dtw1,
                                               const float* __restrict__ dtb1)
{
    const int db  = blockIdx.z;
    const int dir = db >> 1, b = db & 1;
    const int l0  = blockIdx.x * 32;
    const int d0  = blockIdx.y * 64;
    __shared__ float dts[32][49];
    __shared__ float Wts[64][48];
    const float* Wd = dir ? dtw1 : dtw0;
    const float* bd = dir ? dtb1 : dtb0;
    const int t = threadIdx.x;

    for (int idx = t; idx < 32 * 48; idx += 256) {
        int i = idx / 48, r = idx - i * 48;
        dts[i][r] = g_dt[(dir * MROWS + b * LL + l0 + i) * RDT + r];
    }
    for (int idx = t; idx < 64 * 48; idx += 256) {
        int i = idx / 48, r = idx - i * 48;
        Wts[i][r] = Wd[(d0 + i) * RDT + r];
    }
    __syncthreads();

    const int ll = t & 31;
    const int dg = t >> 5;
    float acc[8];
#pragma unroll
    for (int j = 0; j < 8; j++) acc[j] = 0.f;
#pragma unroll
    for (int r = 0; r < 48; r++) {
        float a = dts[ll][r];
#pragma unroll
        for (int j = 0; j < 8; j++) acc[j] = fmaf(a, Wts[dg * 8 + j][r], acc[j]);
    }
#pragma unroll
    for (int j = 0; j < 8; j++) {
        int d = d0 + dg * 8 + j;
        float x = acc[j] + bd[d];
        float sp = (x > 20.f) ? x : log1pf(__expf(x));
        g_delta[((dir * BB + b) * DI + d) * LL + l0 + ll] = sp;
    }
}

// ---------------------------------------------------------------------------
// 6. selective scan
// ---------------------------------------------------------------------------
__global__ void __launch_bounds__(128) k_scan(const float* __restrict__ Alog0,
                                              const float* __restrict__ Alog1,
                                              const float* __restrict__ D0v,
                                              const float* __restrict__ D1v)
{
    const int warp = blockIdx.x * 4 + (threadIdx.x >> 5);
    const int lane = threadIdx.x & 31;
    const int half = lane >> 4;
    const int n    = lane & 15;
    const int ch   = warp * 2 + half;
    const int dir  = ch / (BB * DI);
    const int rem  = ch - dir * (BB * DI);
    const int b    = rem / DI;
    const int d    = rem - b * DI;

    const float An = -__expf((dir ? Alog1 : Alog0)[d * NS + n]);
    const float Dd = (dir ? D1v : D0v)[d];
    const float* dptr = g_delta + ch * LL;
    const float* xptr = g_xc    + ch * LL;
    const float* Bp   = g_Bc + (dir * MROWS + b * LL) * NS + n;
    const float* Cp   = g_Cc + (dir * MROWS + b * LL) * NS + n;
    float* yp = g_y + ch * LL;

    float h = 0.f;
#pragma unroll 2
    for (int l = 0; l < LL; l += 4) {
        float4 d4 = *(const float4*)(dptr + l);
        float4 x4 = *(const float4*)(xptr + l);
        float dl[4] = {d4.x, d4.y, d4.z, d4.w};
        float xl[4] = {x4.x, x4.y, x4.z, x4.w};
        float dA[4], dbx[4], cn[4];
#pragma unroll
        for (int j = 0; j < 4; j++) {
            dA[j]  = __expf(dl[j] * An);
            float bn = *Bp; Bp += NS;
            cn[j]  = *Cp; Cp += NS;
            dbx[j] = dl[j] * xl[j] * bn;
        }
#pragma unroll
        for (int j = 0; j < 4; j++) {
            h = fmaf(dA[j], h, dbx[j]);
            float p = h * cn[j];
            p += __shfl_xor_sync(0xffffffffu, p, 1);
            p += __shfl_xor_sync(0xffffffffu, p, 2);
            p += __shfl_xor_sync(0xffffffffu, p, 4);
            p += __shfl_xor_sync(0xffffffffu, p, 8);
            if (n == 0) yp[l + j] = fmaf(xl[j], Dd, p);
        }
    }
}

// ---------------------------------------------------------------------------
// 7. combine + transpose + bf16 split:
//    yc = (y_f[l] + y_r[L-1-l]) * silu(z); write ych/ycl in [m][k] layout.
//    grid (L/64=16, DI/32=48, B=2), 256 thr
// ---------------------------------------------------------------------------
__global__ void __launch_bounds__(256) k_combine()
{
    const int b  = blockIdx.z;
    const int l0 = blockIdx.x * 64;
    const int d0 = blockIdx.y * 32;
    __shared__ float sv[32][65];
    const int t = threadIdx.x;

    for (int idx = t; idx < 2048; idx += 256) {
        int j  = idx & 63;
        int dc = idx >> 6;
        int d  = d0 + dc;
        float y0 = g_y[((size_t)(b * DI + d)) * LL + l0 + j];
        float y1 = g_y[((size_t)((BB + b) * DI + d)) * LL + (LL - 1 - (l0 + j))];
        float zs = g_zs[((size_t)(b * DI + d)) * LL + l0 + j];
        sv[dc][j] = (y0 + y1) * zs;
    }
    __syncthreads();
    for (int idx = t; idx < 2048; idx += 256) {
        int dc = idx & 31;
        int l  = idx >> 5;
        float v = sv[dc][l];
        __nv_bfloat16 h = __float2bfloat16(v);
        __nv_bfloat16 lo = __float2bfloat16(v - __bfloat162float(h));
        size_t o = (size_t)(b * LL + l0 + l) * DI + d0 + dc;
        g_ych[o] = h;
        g_ycl[o] = lo;
    }
}

// ---------------------------------------------------------------------------
// launch
// ---------------------------------------------------------------------------
extern "C" void kernel_launch(void* const* d_in, const int* in_sizes, int n_in,
                              void* d_out, int out_size)
{
    (void)in_sizes; (void)n_in; (void)out_size;
    const float* hidden   = (const float*)d_in[0];
    const float* in_w     = (const float*)d_in[1];
    const float* conv_w   = (const float*)d_in[2];
    const float* conv_b   = (const float*)d_in[3];
    const float* xproj_w  = (const float*)d_in[4];
    const float* dtproj_w = (const float*)d_in[5];
    const float* dtproj_b = (const float*)d_in[6];
    const float* A_log    = (const float*)d_in[7];
    const float* Dv       = (const float*)d_in[8];
    const float* conv_w_b = (const float*)d_in[9];
    const float* conv_b_b = (const float*)d_in[10];
    const float* xproj_wb = (const float*)d_in[11];
    const float* dtproj_wb= (const float*)d_in[12];
    const float* dtproj_bb= (const float*)d_in[13];
    const float* A_b_log  = (const float*)d_in[14];
    const float* D_b      = (const float*)d_in[15];
    const float* out_w    = (const float*)d_in[16];
    float* out = (float*)d_out;

    k_split_h <<<1536, 256>>>(hidden);
    k_split_wi<<<2304, 256>>>(in_w);
    k_split_wo<<<1152, 256>>>(out_w);
    k_gemm_in<<<dim3((2 * DI) / 64, MROWS / 128), 256>>>();        // (48,16)
    k_conv_zs<<<dim3(16, 48, 6), 256>>>(conv_w, conv_b, conv_w_b, conv_b_b);
    k_xdbl<<<dim3(16, 8, 2), 256>>>(xproj_w, xproj_wb);
    k_xred<<<dim3(1280), 256>>>();
    k_delta<<<dim3(32, 24, 4), 256>>>(dtproj_w, dtproj_b, dtproj_wb, dtproj_bb);
    k_scan<<<dim3(768), 128>>>(A_log, A_b_log, Dv, D_b);
    k_combine<<<dim3(16, 48, 2), 256>>>();
    k_gemm_out<<<dim3(DM / 64, MROWS / 128), 256>>>(out);          // (12,16)
}

// round 10
// speedup vs baseline: 1.1023x; 1.1023x over previous
#include <cuda_runtime.h>
#include <cuda_bf16.h>
#include <cstdint>

// ---------------------------------------------------------------------------
// Bidirectional Mamba (bimamba v2) forward.
//   B=2, L=1024, d_model=768, d_inner=1536, d_state=16, d_conv=4, dt_rank=48
// GEMMs (in_proj, out_proj) via portable mma.sync m16n8k16 bf16 split-2,
// ldmatrix.x4 fragment loads + register-prefetched chunk pipeline.
// Everything else fp32 SIMT (audited pipeline, passed R9 @524us/1.3e-5).
// ---------------------------------------------------------------------------

#define BB    2
#define LL    1024
#define DM    768
#define DI    1536
#define NS    16
#define RDT   48
#define MROWS (BB*LL)          // 2048

// fp32 scratch
__device__ float g_xz[MROWS * 2 * DI];              // (2048, 3072)
__device__ float g_xc[2 * BB * DI * LL];            // [dir][b][d][l]
__device__ float g_zs[BB * DI * LL];                // [b][d][l]
__device__ float g_dt[2 * MROWS * RDT];
__device__ float g_Bc[2 * MROWS * NS];
__device__ float g_Cc[2 * MROWS * NS];
__device__ float g_delta[2 * BB * DI * LL];
__device__ float g_y[2 * BB * DI * LL];
__device__ float g_xpart[8 * 2 * MROWS * 80];

// bf16 split-2 operands for HMMA GEMMs
__device__ __nv_bfloat16 g_hh[MROWS * DM],  g_hl[MROWS * DM];     // hidden [m][k]
__device__ __nv_bfloat16 g_wih[2*DI * DM],  g_wil[2*DI * DM];     // in_proj W [n][k]
__device__ __nv_bfloat16 g_woh[DM * DI],    g_wol[DM * DI];       // out_proj W [n][k]
__device__ __nv_bfloat16 g_ych[MROWS * DI], g_ycl[MROWS * DI];    // combined y [m][k]

// ---------------------------------------------------------------------------
// 0. split fp32 -> bf16 hi/lo
// ---------------------------------------------------------------------------
__device__ __forceinline__ void split_body(const float* __restrict__ s,
                                           __nv_bfloat16* __restrict__ hi,
                                           __nv_bfloat16* __restrict__ lo, int n)
{
    int i = (blockIdx.x * blockDim.x + threadIdx.x) * 4;
    if (i >= n) return;
    float4 v = *(const float4*)(s + i);
    ushort4 H, L;
    {
        __nv_bfloat16 h = __float2bfloat16(v.x);
        H.x = __bfloat16_as_ushort(h);
        L.x = __bfloat16_as_ushort(__float2bfloat16(v.x - __bfloat162float(h)));
    }
    {
        __nv_bfloat16 h = __float2bfloat16(v.y);
        H.y = __bfloat16_as_ushort(h);
        L.y = __bfloat16_as_ushort(__float2bfloat16(v.y - __bfloat162float(h)));
    }
    {
        __nv_bfloat16 h = __float2bfloat16(v.z);
        H.z = __bfloat16_as_ushort(h);
        L.z = __bfloat16_as_ushort(__float2bfloat16(v.z - __bfloat162float(h)));
    }
    {
        __nv_bfloat16 h = __float2bfloat16(v.w);
        H.w = __bfloat16_as_ushort(h);
        L.w = __bfloat16_as_ushort(__float2bfloat16(v.w - __bfloat162float(h)));
    }
    *(ushort4*)((unsigned short*)hi + i) = H;
    *(ushort4*)((unsigned short*)lo + i) = L;
}
__global__ void k_split_h(const float* __restrict__ s)  { split_body(s, g_hh,  g_hl,  MROWS * DM); }
__global__ void k_split_wi(const float* __restrict__ s) { split_body(s, g_wih, g_wil, 2 * DI * DM); }
__global__ void k_split_wo(const float* __restrict__ s) { split_body(s, g_woh, g_wol, DM * DI); }

// ---------------------------------------------------------------------------
// mma.sync m16n8k16 row.col f32.bf16.bf16.f32  +  ldmatrix.x4
// ---------------------------------------------------------------------------
__device__ __forceinline__ void mma16816(float* c, const uint32_t* a, const uint32_t* b)
{
    asm volatile(
        "mma.sync.aligned.m16n8k16.row.col.f32.bf16.bf16.f32 "
        "{%0,%1,%2,%3}, {%4,%5,%6,%7}, {%8,%9}, {%0,%1,%2,%3};"
        : "+f"(c[0]), "+f"(c[1]), "+f"(c[2]), "+f"(c[3])
        : "r"(a[0]), "r"(a[1]), "r"(a[2]), "r"(a[3]), "r"(b[0]), "r"(b[1]));
}

__device__ __forceinline__ void ldsm4(uint32_t* r, uint32_t a)
{
    asm volatile("ldmatrix.sync.aligned.m8n8.x4.shared.b16 {%0,%1,%2,%3}, [%4];"
        : "=r"(r[0]), "=r"(r[1]), "=r"(r[2]), "=r"(r[3]) : "r"(a));
}

// ---------------------------------------------------------------------------
// HMMA split-2 GEMM:  C[m][n] = sum_k A[m][k] * W[n][k]
// CTA tile 128x64, 8 warps (4 m x 2 n) of 32x32. K-chunk 32.
// smem rows padded to ASTR=40 bf16 (80B): uint4-aligned; ldmatrix row
// addresses hit distinct 16B banks ({0,5,2,7,4,1,6,3} mod 8) -> conflict-free.
// Chunk pipeline: regs for chunk c+1 LDG'd while chunk c computes.
// Per k16 step & warp: 8 ldmatrix.x4 + 24 mma ({AhBh, AhBl, AlBh}).
// ---------------------------------------------------------------------------
#define ASTR 40   // smem row stride in bf16

__device__ __forceinline__ void gemm_mma_body(const __nv_bfloat16* __restrict__ Ah,
                                              const __nv_bfloat16* __restrict__ Al,
                                              const __nv_bfloat16* __restrict__ Wh,
                                              const __nv_bfloat16* __restrict__ Wl,
                                              float* __restrict__ C,
                                              const int K, const int N)
{
    __shared__ __align__(16) __nv_bfloat16 sAh[128 * ASTR];
    __shared__ __align__(16) __nv_bfloat16 sAl[128 * ASTR];
    __shared__ __align__(16) __nv_bfloat16 sWh[64 * ASTR];
    __shared__ __align__(16) __nv_bfloat16 sWl[64 * ASTR];

    const int t    = threadIdx.x;
    const int wid  = t >> 5;
    const int lane = t & 31;
    const int wm   = wid & 3;            // 0..3 -> m offset wm*32
    const int wn   = wid >> 2;           // 0..1 -> n offset wn*32
    const int g    = lane >> 2;          // group 0..7
    const int t2   = (lane & 3) * 2;     // 0,2,4,6
    const int bm   = blockIdx.y * 128;
    const int bn   = blockIdx.x * 64;

    // smem 32-bit addresses for ldmatrix
    const uint32_t sAh32 = (uint32_t)__cvta_generic_to_shared(sAh);
    const uint32_t sAl32 = (uint32_t)__cvta_generic_to_shared(sAl);
    const uint32_t sWh32 = (uint32_t)__cvta_generic_to_shared(sWh);
    const uint32_t sWl32 = (uint32_t)__cvta_generic_to_shared(sWl);
    // A frag lane pattern: lanes 0-7 rows r0..r0+7 @k0 (a0), 8-15 rows+8 (a1),
    // 16-23 rows @k0+8 (a2), 24-31 rows+8 @k0+8 (a3)
    const int arow = lane & 15, akh = lane >> 4;
    uint32_t aofs[2];
#pragma unroll
    for (int mt = 0; mt < 2; mt++)
        aofs[mt] = ((wm * 32 + mt * 16 + arow) * ASTR + akh * 8) * 2;
    // B frag lane pattern (pair p covers nt=2p,2p+1):
    // lanes 0-7 rows n0..+7 @k0 (b[2p]0), 8-15 same rows @k0+8 (b[2p]1),
    // 16-23 rows+8 @k0 (b[2p+1]0), 24-31 rows+8 @k0+8 (b[2p+1]1)
    const int brow = (lane & 7) + ((lane >> 4) << 3);
    const int bkh  = (lane >> 3) & 1;
    uint32_t bofs[2];
#pragma unroll
    for (int p = 0; p < 2; p++)
        bofs[p] = ((wn * 32 + p * 16 + brow) * ASTR + bkh * 8) * 2;

    // fill-role indices (per thread): A 2 rows, W 1 row segment
    const int farow0 = t >> 2, faseg = t & 3;          // A: idx t and t+256

    float acc[2][4][4];
#pragma unroll
    for (int mt = 0; mt < 2; mt++)
#pragma unroll
        for (int nt = 0; nt < 4; nt++)
#pragma unroll
            for (int q = 0; q < 4; q++) acc[mt][nt][q] = 0.f;

    const int NC = K / 32;
    uint4 pah[2], pal[2], pwh, pwl;

    // prologue: prefetch chunk 0
#pragma unroll
    for (int i = 0; i < 2; i++) {
        const int row = farow0 + i * 64;
        const size_t gofs = (size_t)(bm + row) * K + faseg * 8;
        pah[i] = *(const uint4*)(Ah + gofs);
        pal[i] = *(const uint4*)(Al + gofs);
    }
    {
        const size_t gofs = (size_t)(bn + farow0) * K + faseg * 8;
        pwh = *(const uint4*)(Wh + gofs);
        pwl = *(const uint4*)(Wl + gofs);
    }

    for (int c = 0; c < NC; c++) {
        __syncthreads();                      // previous chunk's compute done
#pragma unroll
        for (int i = 0; i < 2; i++) {
            const int row = farow0 + i * 64;
            *(uint4*)(sAh + row * ASTR + faseg * 8) = pah[i];
            *(uint4*)(sAl + row * ASTR + faseg * 8) = pal[i];
        }
        *(uint4*)(sWh + farow0 * ASTR + faseg * 8) = pwh;
        *(uint4*)(sWl + farow0 * ASTR + faseg * 8) = pwl;
        __syncthreads();

        if (c + 1 < NC) {                     // prefetch next chunk (overlaps MMA)
            const int k0g = (c + 1) * 32;
#pragma unroll
            for (int i = 0; i < 2; i++) {
                const int row = farow0 + i * 64;
                const size_t gofs = (size_t)(bm + row) * K + k0g + faseg * 8;
                pah[i] = *(const uint4*)(Ah + gofs);
                pal[i] = *(const uint4*)(Al + gofs);
            }
            const size_t gofs = (size_t)(bn + farow0) * K + k0g + faseg * 8;
            pwh = *(const uint4*)(Wh + gofs);
            pwl = *(const uint4*)(Wl + gofs);
        }

#pragma unroll
        for (int ks = 0; ks < 2; ks++) {
            const uint32_t kb = ks * 32;      // 16 bf16 = 32 bytes
            uint32_t ah[2][4], al[2][4], bh[2][4], bl[2][4];
#pragma unroll
            for (int mt = 0; mt < 2; mt++) {
                ldsm4(ah[mt], sAh32 + aofs[mt] + kb);
                ldsm4(al[mt], sAl32 + aofs[mt] + kb);
            }
#pragma unroll
            for (int p = 0; p < 2; p++) {
                ldsm4(bh[p], sWh32 + bofs[p] + kb);
                ldsm4(bl[p], sWl32 + bofs[p] + kb);
            }
#pragma unroll
            for (int mt = 0; mt < 2; mt++)
#pragma unroll
                for (int nt = 0; nt < 4; nt++) {
                    const int p = nt >> 1, h = (nt & 1) * 2;
                    mma16816(acc[mt][nt], ah[mt], &bh[p][h]);
                    mma16816(acc[mt][nt], ah[mt], &bl[p][h]);
                    mma16816(acc[mt][nt], al[mt], &bh[p][h]);
                }
        }
    }

#pragma unroll
    for (int mt = 0; mt < 2; mt++) {
        const int row = bm + wm * 32 + mt * 16 + g;
#pragma unroll
        for (int nt = 0; nt < 4; nt++) {
            const int col = bn + wn * 32 + nt * 8 + t2;
            *(float2*)(C + (size_t)row * N + col)       = make_float2(acc[mt][nt][0], acc[mt][nt][1]);
            *(float2*)(C + (size_t)(row + 8) * N + col) = make_float2(acc[mt][nt][2], acc[mt][nt][3]);
        }
    }
}

__global__ void __launch_bounds__(256) k_gemm_in()
{ gemm_mma_body(g_hh, g_hl, g_wih, g_wil, g_xz, DM, 2 * DI); }

__global__ void __launch_bounds__(256) k_gemm_out(float* __restrict__ C)
{ gemm_mma_body(g_ych, g_ycl, g_woh, g_wol, C, DI, DM); }

// ---------------------------------------------------------------------------
// 2. conv (both dirs) + silu(z), transpose to channel-major.
// ---------------------------------------------------------------------------
__device__ __forceinline__ float siluf(float v) { return v / (1.f + __expf(-v)); }

__global__ void __launch_bounds__(256) k_conv_zs(const float* __restrict__ cw0,
                                                 const float* __restrict__ cb0,
                                                 const float* __restrict__ cw1,
                                                 const float* __restrict__ cb1)
{
    const int task = blockIdx.z % 3;
    const int b    = blockIdx.z / 3;
    const int l0   = blockIdx.x * 64;
    const int d0   = blockIdx.y * 32;
    __shared__ float sx[68][33];
    const int t = threadIdx.x;

    if (task < 2) {
        const int dir = task;
        for (int idx = t; idx < 67 * 32; idx += 256) {
            int j  = idx >> 5;
            int dc = idx & 31;
            int ls = l0 + j - 3;
            float v = 0.f;
            if (ls >= 0 && ls < LL) {
                int src = dir ? (LL - 1 - ls) : ls;
                v = g_xz[(b * LL + src) * (2 * DI) + d0 + dc];
            }
            sx[j][dc] = v;
        }
        __syncthreads();
        const float* cw = dir ? cw1 : cw0;
        const float* cb = dir ? cb1 : cb0;
        const int ll = t & 63;
        const int dg = t >> 6;
#pragma unroll
        for (int i = 0; i < 8; i++) {
            int dc = dg * 8 + i;
            int d  = d0 + dc;
            float acc = cb[d];
            acc = fmaf(cw[d * 4 + 0], sx[ll + 0][dc], acc);
            acc = fmaf(cw[d * 4 + 1], sx[ll + 1][dc], acc);
            acc = fmaf(cw[d * 4 + 2], sx[ll + 2][dc], acc);
            acc = fmaf(cw[d * 4 + 3], sx[ll + 3][dc], acc);
            g_xc[((dir * BB + b) * DI + d) * LL + l0 + ll] = siluf(acc);
        }
    } else {
        for (int idx = t; idx < 64 * 32; idx += 256) {
            int j  = idx >> 5;
            int dc = idx & 31;
            sx[j][dc] = g_xz[(b * LL + l0 + j) * (2 * DI) + DI + d0 + dc];
        }
        __syncthreads();
        const int ll = t & 63;
        const int dg = t >> 6;
#pragma unroll
        for (int i = 0; i < 8; i++) {
            int dc = dg * 8 + i;
            int d  = d0 + dc;
            g_zs[(b * DI + d) * LL + l0 + ll] = siluf(sx[ll][dc]);
        }
    }
}

// ---------------------------------------------------------------------------
// 3/4. x_dbl GEMM with K-split + reduce
// ---------------------------------------------------------------------------
__global__ void __launch_bounds__(256) k_xdbl(const float* __restrict__ W0,
                                              const float* __restrict__ W1)
{
    const int dir = blockIdx.z;
    const int bm  = blockIdx.x * 128;
    const int b   = bm >> 10;
    const int lb  = bm & 1023;
    const int ks  = blockIdx.y;
    const float* W = dir ? W1 : W0;

    __shared__ __align__(16) float As[8][128];
    __shared__ float Ws[8][80];
    const int t  = threadIdx.x;
    const int kl = t >> 5;
    const int lq = (t & 31) * 4;
    const int ty = t >> 4, tx = t & 15;

    float acc[8][5];
#pragma unroll
    for (int i = 0; i < 8; i++)
#pragma unroll
        for (int j = 0; j < 5; j++) acc[i][j] = 0.f;

    const int kend = ks * 192 + 192;
    for (int k0 = ks * 192; k0 < kend; k0 += 8) {
        float4 a4 = *(const float4*)(g_xc + ((dir * BB + b) * DI + k0 + kl) * LL + lb + lq);
        *(float4*)&As[kl][lq] = a4;
        if (t < 160) {
            int n  = t >> 1;
            int kq = (t & 1) * 4;
            float4 w4 = *(const float4*)(W + n * DI + k0 + kq);
            Ws[kq + 0][n] = w4.x; Ws[kq + 1][n] = w4.y;
            Ws[kq + 2][n] = w4.z; Ws[kq + 3][n] = w4.w;
        }
        __syncthreads();
#pragma unroll
        for (int kk = 0; kk < 8; kk++) {
            float br[5];
#pragma unroll
            for (int j = 0; j < 5; j++) br[j] = Ws[kk][tx * 5 + j];
#pragma unroll
            for (int i = 0; i < 8; i++) {
                float a = As[kk][ty * 8 + i];
#pragma unroll
                for (int j = 0; j < 5; j++) acc[i][j] = fmaf(a, br[j], acc[i][j]);
            }
        }
        __syncthreads();
    }
    float* part = g_xpart + ks * (2 * MROWS * 80);
#pragma unroll
    for (int i = 0; i < 8; i++) {
        int row = dir * MROWS + bm + ty * 8 + i;
#pragma unroll
        for (int j = 0; j < 5; j++)
            part[row * 80 + tx * 5 + j] = acc[i][j];
    }
}

__global__ void k_xred()
{
    int o = blockIdx.x * blockDim.x + threadIdx.x;
    if (o >= 2 * MROWS * 80) return;
    float s = 0.f;
#pragma unroll
    for (int p = 0; p < 8; p++) s += g_xpart[p * (2 * MROWS * 80) + o];
    int row = o / 80;
    int n   = o - row * 80;
    if (n < 48)       g_dt[row * RDT + n] = s;
    else if (n < 64)  g_Bc[row * NS + n - 48] = s;
    else              g_Cc[row * NS + n - 64] = s;
}

// ---------------------------------------------------------------------------
// 5. delta GEMM (K=48) + softplus, transposed store
// ---------------------------------------------------------------------------
__global__ void __launch_bounds__(256) k_delta(const float* __restrict__ dtw0,
                                               const float* __restrict__ dtb0,
                                               const float* __restrict__ dtw1,
                                               const float* __restrict__ dtb1)
{
    const int db  = blockIdx.z;
    const int dir = db >> 1, b = db & 1;
    const int l0  = blockIdx.x * 32;
    const int d0  = blockIdx.y * 64;
    __shared__ float dts[32][49];
    __shared__ float Wts[64][48];
    const float* Wd = dir ? dtw1 : dtw0;
    const float* bd = dir ? dtb1 : dtb0;
    const int t = threadIdx.x;

    for (int idx = t; idx < 32 * 48; idx += 256) {
        int i = idx / 48, r = idx - i * 48;
        dts[i][r] = g_dt[(dir * MROWS + b * LL + l0 + i) * RDT + r];
    }
    for (int idx = t; idx < 64 * 48; idx += 256) {
        int i = idx / 48, r = idx - i * 48;
        Wts[i][r] = Wd[(d0 + i) * RDT + r];
    }
    __syncthreads();

    const int ll = t & 31;
    const int dg = t >> 5;
    float acc[8];
#pragma unroll
    for (int j = 0; j < 8; j++) acc[j] = 0.f;
#pragma unroll
    for (int r = 0; r < 48; r++) {
        float a = dts[ll][r];
#pragma unroll
        for (int j = 0; j < 8; j++) acc[j] = fmaf(a, Wts[dg * 8 + j][r], acc[j]);
    }
#pragma unroll
    for (int j = 0; j < 8; j++) {
        int d = d0 + dg * 8 + j;
        float x = acc[j] + bd[d];
        float sp = (x > 20.f) ? x : log1pf(__expf(x));
        g_delta[((dir * BB + b) * DI + d) * LL + l0 + ll] = sp;
    }
}

// ---------------------------------------------------------------------------
// 6. selective scan
// ---------------------------------------------------------------------------
__global__ void __launch_bounds__(128) k_scan(const float* __restrict__ Alog0,
                                              const float* __restrict__ Alog1,
                                              const float* __restrict__ D0v,
                                              const float* __restrict__ D1v)
{
    const int warp = blockIdx.x * 4 + (threadIdx.x >> 5);
    const int lane = threadIdx.x & 31;
    const int half = lane >> 4;
    const int n    = lane & 15;
    const int ch   = warp * 2 + half;
    const int dir  = ch / (BB * DI);
    const int rem  = ch - dir * (BB * DI);
    const int b    = rem / DI;
    const int d    = rem - b * DI;

    const float An = -__expf((dir ? Alog1 : Alog0)[d * NS + n]);
    const float Dd = (dir ? D1v : D0v)[d];
    const float* dptr = g_delta + ch * LL;
    const float* xptr = g_xc    + ch * LL;
    const float* Bp   = g_Bc + (dir * MROWS + b * LL) * NS + n;
    const float* Cp   = g_Cc + (dir * MROWS + b * LL) * NS + n;
    float* yp = g_y + ch * LL;

    float h = 0.f;
#pragma unroll 2
    for (int l = 0; l < LL; l += 4) {
        float4 d4 = *(const float4*)(dptr + l);
        float4 x4 = *(const float4*)(xptr + l);
        float dl[4] = {d4.x, d4.y, d4.z, d4.w};
        float xl[4] = {x4.x, x4.y, x4.z, x4.w};
        float dA[4], dbx[4], cn[4];
#pragma unroll
        for (int j = 0; j < 4; j++) {
            dA[j]  = __expf(dl[j] * An);
            float bn = *Bp; Bp += NS;
            cn[j]  = *Cp; Cp += NS;
            dbx[j] = dl[j] * xl[j] * bn;
        }
#pragma unroll
        for (int j = 0; j < 4; j++) {
            h = fmaf(dA[j], h, dbx[j]);
            float p = h * cn[j];
            p += __shfl_xor_sync(0xffffffffu, p, 1);
            p += __shfl_xor_sync(0xffffffffu, p, 2);
            p += __shfl_xor_sync(0xffffffffu, p, 4);
            p += __shfl_xor_sync(0xffffffffu, p, 8);
            if (n == 0) yp[l + j] = fmaf(xl[j], Dd, p);
        }
    }
}

// ---------------------------------------------------------------------------
// 7. combine + transpose + bf16 split:
//    yc = (y_f[l] + y_r[L-1-l]) * silu(z); write ych/ycl in [m][k] layout.
//    grid (L/64=16, DI/32=48, B=2), 256 thr
// ---------------------------------------------------------------------------
__global__ void __launch_bounds__(256) k_combine()
{
    const int b  = blockIdx.z;
    const int l0 = blockIdx.x * 64;
    const int d0 = blockIdx.y * 32;
    __shared__ float sv[32][65];
    const int t = threadIdx.x;

    for (int idx = t; idx < 2048; idx += 256) {
        int j  = idx & 63;
        int dc = idx >> 6;
        int d  = d0 + dc;
        float y0 = g_y[((size_t)(b * DI + d)) * LL + l0 + j];
        float y1 = g_y[((size_t)((BB + b) * DI + d)) * LL + (LL - 1 - (l0 + j))];
        float zs = g_zs[((size_t)(b * DI + d)) * LL + l0 + j];
        sv[dc][j] = (y0 + y1) * zs;
    }
    __syncthreads();
    for (int idx = t; idx < 2048; idx += 256) {
        int dc = idx & 31;
        int l  = idx >> 5;
        float v = sv[dc][l];
        __nv_bfloat16 h = __float2bfloat16(v);
        __nv_bfloat16 lo = __float2bfloat16(v - __bfloat162float(h));
        size_t o = (size_t)(b * LL + l0 + l) * DI + d0 + dc;
        g_ych[o] = h;
        g_ycl[o] = lo;
    }
}

// ---------------------------------------------------------------------------
// launch
// ---------------------------------------------------------------------------
extern "C" void kernel_launch(void* const* d_in, const int* in_sizes, int n_in,
                              void* d_out, int out_size)
{
    (void)in_sizes; (void)n_in; (void)out_size;
    const float* hidden   = (const float*)d_in[0];
    const float* in_w     = (const float*)d_in[1];
    const float* conv_w   = (const float*)d_in[2];
    const float* conv_b   = (const float*)d_in[3];
    const float* xproj_w  = (const float*)d_in[4];
    const float* dtproj_w = (const float*)d_in[5];
    const float* dtproj_b = (const float*)d_in[6];
    const float* A_log    = (const float*)d_in[7];
    const float* Dv       = (const float*)d_in[8];
    const float* conv_w_b = (const float*)d_in[9];
    const float* conv_b_b = (const float*)d_in[10];
    const float* xproj_wb = (const float*)d_in[11];
    const float* dtproj_wb= (const float*)d_in[12];
    const float* dtproj_bb= (const float*)d_in[13];
    const float* A_b_log  = (const float*)d_in[14];
    const float* D_b      = (const float*)d_in[15];
    const float* out_w    = (const float*)d_in[16];
    float* out = (float*)d_out;

    k_split_h <<<1536, 256>>>(hidden);
    k_split_wi<<<2304, 256>>>(in_w);
    k_split_wo<<<1152, 256>>>(out_w);
    k_gemm_in<<<dim3((2 * DI) / 64, MROWS / 128), 256>>>();        // (48,16)
    k_conv_zs<<<dim3(16, 48, 6), 256>>>(conv_w, conv_b, conv_w_b, conv_b_b);
    k_xdbl<<<dim3(16, 8, 2), 256>>>(xproj_w, xproj_wb);
    k_xred<<<dim3(1280), 256>>>();
    k_delta<<<dim3(32, 24, 4), 256>>>(dtproj_w, dtproj_b, dtproj_wb, dtproj_bb);
    k_scan<<<dim3(768), 128>>>(A_log, A_b_log, Dv, D_b);
    k_combine<<<dim3(16, 48, 2), 256>>>();
    k_gemm_out<<<dim3(DM / 64, MROWS / 128), 256>>>(out);          // (12,16)
}